// round 15
// baseline (speedup 1.0000x reference)
#include <cuda_runtime.h>
#include <math.h>
#include <float.h>

#define HIDDEN 5120
#define NH 40
#define HD 128
#define MAXL 2048
#define QL 8
#define CHUNK 256
#define NCHUNK (MAXL / CHUNK)
#define QK_SCALE 0.08838834764831845f  // 1/sqrt(128)
#define C4 (HIDDEN / 4)                // 1280 float4 per row
#define ROWS 4
#define GT 512                         // 128 col-slots x 4 q-pairs
#define COLS 128                       // float4 columns per iter
#define GITER 10                       // C4 / COLS

// packed f32x2 FMA
#define FMAX2(acc, a, b) \
    asm("fma.rn.f32x2 %0, %1, %2, %0;" : "+l"(acc) : "l"(a), "l"(b))

__device__ __forceinline__ float x2lo(unsigned long long v) {
    return __uint_as_float((unsigned)(v & 0xffffffffu));
}
__device__ __forceinline__ float x2hi(unsigned long long v) {
    return __uint_as_float((unsigned)(v >> 32));
}
__device__ __forceinline__ float x2sum(unsigned long long v) {
    return x2lo(v) + x2hi(v);
}
__device__ __forceinline__ unsigned long long f32dup(float p) {
    unsigned b = __float_as_uint(p);
    return ((unsigned long long)b << 32) | b;
}

// ---------------- device scratch (no allocs allowed) ----------------
__device__ float g_q[NH * QL * HD];                    // [h][q][d], pre-scaled
__device__ float g_k[NH * QL * HD];                    // new K rows  [h][q][d]
__device__ float g_v[NH * QL * HD];                    // new V rows  [h][q][d]
__device__ float g_opart[NH * QL * NCHUNK * HD];       // [h][q][chunk][d]
__device__ float g_m[NH * QL * NCHUNK];                // chunk max
__device__ float g_l[NH * QL * NCHUNK];                // chunk expsum
__device__ float g_ctx[QL * HIDDEN];                   // attention out [q][h*128+d]

// ---------------------------------------------------------------
// Persistent GEMV, M=8: Y[q][r] = dot(X[q], W[r]).
// R14 layout (port-minimal: W direct __ldcg to regs = 1 L1tex pass;
// X in smem, ROWS=4 -> X LDS = 2x W bytes, total ~3x vs R12's 6x)
// + DEPTH-5 compile-time register pipeline (wv0..wv4, unroll-by-10):
// wload(m+5) -> consume(m+5) distance = 4 sub-iters, covering DRAM
// latency that R14's depth-2 could not.
// grid = #SMs, 1 CTA/SM, 512 thr = 128 col-slots x 4 q-pairs.
// acc = 4 rows x 2q f32x2 = 8 b64; bufs 5x4 float4 = 80 regs.
// mode 0: W_pack -> g_q/g_k/g_v.  mode 1: W_o, X=g_ctx -> Y.
// Dynamic smem = 8*1280*16 = 163840 B (opt-in).
// ---------------------------------------------------------------
__global__ void __launch_bounds__(GT, 1) gemv_kernel(
    const float* __restrict__ Xin, const float* __restrict__ W,
    float* __restrict__ Y, int mode, int ngrp)
{
    extern __shared__ float4 sX4[];              // [QL][C4]
    __shared__ float sred[16][32];               // 16 warps x (4r * 8q)

    int tid = threadIdx.x, bid = blockIdx.x, grid = gridDim.x;
    int qp = tid & 3;                            // q-pair 0..3
    int cl = tid >> 2;                           // column slot 0..127
    int lane = tid & 31, warp = tid >> 5;
    int q0 = qp * 2;
    const float4* __restrict__ X4 =
        reinterpret_cast<const float4*>((mode == 1) ? g_ctx : Xin);

    // ---- X preload into smem (one-time) ----
#pragma unroll
    for (int i = 0; i < (QL * C4) / GT; i++) {
        int idx = tid + i * GT;
        sX4[idx] = __ldg(X4 + idx);
    }
    __syncthreads();

    int nloc = (ngrp - bid - 1) / grid + 1;      // groups owned by this CTA
    int total = nloc * GITER;                    // multiple of 10, >= 10

    // W load for logical iter idx into a named register buffer
    auto wload = [&](int idx, float4* dst) {
        int j = idx / GITER, iti = idx - j * GITER;
        size_t rowbase = (size_t)(bid + (size_t)j * grid) * ROWS;
        const float4* g = reinterpret_cast<const float4*>(
            W + rowbase * HIDDEN) + iti * COLS + cl;
#pragma unroll
        for (int r = 0; r < ROWS; r++)
            dst[r] = __ldcg(g + (size_t)r * C4);
    };

    unsigned long long acc[ROWS][2];             // f32x2 column pairs
#pragma unroll
    for (int r = 0; r < ROWS; r++) { acc[r][0] = 0ull; acc[r][1] = 0ull; }

    auto consume = [&](int m, const float4* wv) {
        int j = m / GITER, it = m - j * GITER;
        int c4 = cl + it * COLS;
        ulonglong2 xa = *reinterpret_cast<const ulonglong2*>(
            &sX4[q0 * C4 + c4]);
        ulonglong2 xb = *reinterpret_cast<const ulonglong2*>(
            &sX4[(q0 + 1) * C4 + c4]);
#pragma unroll
        for (int r = 0; r < ROWS; r++) {
            ulonglong2 w2 = *reinterpret_cast<const ulonglong2*>(&wv[r]);
            FMAX2(acc[r][0], w2.x, xa.x);
            FMAX2(acc[r][0], w2.y, xa.y);
            FMAX2(acc[r][1], w2.x, xb.x);
            FMAX2(acc[r][1], w2.y, xb.y);
        }
    };

    auto flush = [&](int j) {
        long rowbase = (long)(bid + (long)j * grid) * ROWS;
        __syncthreads();   // protect sred from prev group's readers
#pragma unroll
        for (int r = 0; r < ROWS; r++) {
#pragma unroll
            for (int s = 0; s < 2; s++) {
                float v = x2sum(acc[r][s]);
                v += __shfl_down_sync(0xffffffffu, v, 16);
                v += __shfl_down_sync(0xffffffffu, v, 8);
                v += __shfl_down_sync(0xffffffffu, v, 4);
                if (lane < 4)
                    sred[warp][r * QL + lane * 2 + s] = v;
                acc[r][s] = 0ull;
            }
        }
        __syncthreads();
        if (tid < 32) {
            float v = 0.0f;
#pragma unroll
            for (int w = 0; w < 16; w++) v += sred[w][tid];
            long r = rowbase + (tid >> 3);
            int q = tid & 7;
            if (mode == 0) {
                int sect = (int)(r / HIDDEN);      // 0=q, 1=k, 2=v
                int f = (int)(r % HIDDEN);
                int h = f / HD, d = f % HD;
                int o = (h * QL + q) * HD + d;
                if (sect == 0)      g_q[o] = v * QK_SCALE;
                else if (sect == 1) g_k[o] = v;
                else                g_v[o] = v;
            } else {
                Y[(long)q * HIDDEN + r] = v;
            }
        }
    };

    // ---- depth-5 named register buffers (all indices compile-time) ----
    float4 wv0[ROWS], wv1[ROWS], wv2[ROWS], wv3[ROWS], wv4[ROWS];
    wload(0, wv0); wload(1, wv1); wload(2, wv2);
    wload(3, wv3); wload(4, wv4);

#define GEMV_SUB(m, wv)                                   \
    consume((m), wv);                                     \
    if ((m) + 5 < total) wload((m) + 5, wv);

    for (int n = 0; n < total; n += 10) {
        // sub-iters n .. n+4
        GEMV_SUB(n + 0, wv0)
        GEMV_SUB(n + 1, wv1)
        GEMV_SUB(n + 2, wv2)
        GEMV_SUB(n + 3, wv3)
        GEMV_SUB(n + 4, wv4)
        // sub-iters n+5 .. n+9 (group boundary at n+9)
        GEMV_SUB(n + 5, wv0)
        GEMV_SUB(n + 6, wv1)
        GEMV_SUB(n + 7, wv2)
        GEMV_SUB(n + 8, wv3)
        GEMV_SUB(n + 9, wv4)
        flush(n / 10);
    }
#undef GEMV_SUB
}

// ---------------------------------------------------------------
// Split-KV attention: block = (chunk of 256 keys, head). f32x2 in both
// matmul phases; probs stored pre-duplicated (p,p) in smem for PV phase.
// ---------------------------------------------------------------
__global__ void __launch_bounds__(256) attn_kernel(
    const float* __restrict__ kc, const float* __restrict__ vc,
    const float* __restrict__ mask, const int* __restrict__ ipos)
{
    int chunk = blockIdx.x;
    int h = blockIdx.y;
    int tid = threadIdx.x;
    int warp = tid >> 5, lane = tid & 31;

    __shared__ float qs[QL][HD];                    // 4 KB
    __shared__ float scf[QL][CHUNK];                // 8 KB scores
    __shared__ unsigned long long sc2[QL][CHUNK];   // 16 KB dup probs
    __shared__ float4 red[8][QL][32];               // 32 KB partial O
    __shared__ int pos[QL];
    __shared__ int sel[CHUNK];

    if (tid == 0) {
        bool is64 = (ipos[1] == 0);     // int64 little-endian high word
#pragma unroll
        for (int j = 0; j < QL; j++) pos[j] = is64 ? ipos[2 * j] : ipos[j];
    }
    for (int i = tid; i < QL * HD; i += 256) qs[0][i] = g_q[h * QL * HD + i];
    __syncthreads();

    // ---- scores: one key per thread, f32x2 pairs over d ----
    int key = chunk * CHUNK + tid;
    int s = -1;
#pragma unroll
    for (int j = 0; j < QL; j++) if (pos[j] == key) s = j;
    sel[tid] = s;

    const ulonglong2* kp = reinterpret_cast<const ulonglong2*>(
        (s >= 0) ? &g_k[(h * QL + s) * HD]
                 : &kc[((size_t)h * MAXL + key) * HD]);
    unsigned long long a2[QL];
#pragma unroll
    for (int q = 0; q < QL; q++) a2[q] = 0ull;
#pragma unroll
    for (int c = 0; c < HD / 4; c += 8) {
        ulonglong2 kv[8];
#pragma unroll
        for (int u = 0; u < 8; u++) kv[u] = __ldcg(kp + c + u);
#pragma unroll
        for (int u = 0; u < 8; u++) {
#pragma unroll
            for (int q = 0; q < QL; q++) {
                ulonglong2 qv = *reinterpret_cast<const ulonglong2*>(
                    &qs[q][(c + u) * 4]);
                FMAX2(a2[q], kv[u].x, qv.x);
                FMAX2(a2[q], kv[u].y, qv.y);
            }
        }
    }
#pragma unroll
    for (int q = 0; q < QL; q++) {
        float m = __ldcg(&mask[((size_t)h * MAXL + pos[q]) * MAXL + key]);
        scf[q][tid] = fmaxf(x2sum(a2[q]) + m, -FLT_MAX);
    }
    __syncthreads();

    // ---- softmax stats: warp q handles query q; write dup probs ----
    {
        float m = -FLT_MAX;
#pragma unroll
        for (int i = 0; i < CHUNK / 32; i++) m = fmaxf(m, scf[warp][lane + i * 32]);
#pragma unroll
        for (int o = 16; o > 0; o >>= 1) m = fmaxf(m, __shfl_xor_sync(0xffffffffu, m, o));
        float l = 0.0f;
#pragma unroll
        for (int i = 0; i < CHUNK / 32; i++) {
            float p = __expf(scf[warp][lane + i * 32] - m);
            sc2[warp][lane + i * 32] = f32dup(p);
            l += p;
        }
#pragma unroll
        for (int o = 16; o > 0; o >>= 1) l += __shfl_xor_sync(0xffffffffu, l, o);
        if (lane == 0) {
            g_m[(h * QL + warp) * NCHUNK + chunk] = m;
            g_l[(h * QL + warp) * NCHUNK + chunk] = l;
        }
    }
    __syncthreads();

    // ---- partial O = P^T V. warp w: keys w,w+8,...; lane: d-float4 ----
    unsigned long long acc[QL][2];     // 2 d-pairs per lane
#pragma unroll
    for (int q = 0; q < QL; q++) { acc[q][0] = 0ull; acc[q][1] = 0ull; }

#pragma unroll
    for (int j = 0; j < 32; j += 4) {
        ulonglong2 vv[4];
#pragma unroll
        for (int u = 0; u < 4; u++) {
            int k = warp + 8 * (j + u);
            int sv = sel[k];
            int kk = chunk * CHUNK + k;
            const ulonglong2* vp = reinterpret_cast<const ulonglong2*>(
                (sv >= 0) ? &g_v[(h * QL + sv) * HD]
                          : &vc[((size_t)h * MAXL + kk) * HD]);
            vv[u] = __ldcg(vp + lane);
        }
#pragma unroll
        for (int u = 0; u < 4; u++) {
            int k = warp + 8 * (j + u);
#pragma unroll
            for (int q = 0; q < QL; q++) {
                unsigned long long p2 = sc2[q][k];
                FMAX2(acc[q][0], p2, vv[u].x);
                FMAX2(acc[q][1], p2, vv[u].y);
            }
        }
    }
#pragma unroll
    for (int q = 0; q < QL; q++)
        red[warp][q][lane] = make_float4(x2lo(acc[q][0]), x2hi(acc[q][0]),
                                         x2lo(acc[q][1]), x2hi(acc[q][1]));
    __syncthreads();

    // reduce 8 warps: thread t handles (q, d4) = (t/32, t%32)
    {
        int q = tid >> 5, d4 = tid & 31;
        float4 o = red[0][q][d4];
#pragma unroll
        for (int w = 1; w < 8; w++) {
            float4 v = red[w][q][d4];
            o.x += v.x; o.y += v.y; o.z += v.z; o.w += v.w;
        }
        reinterpret_cast<float4*>(
            &g_opart[((h * QL + q) * NCHUNK + chunk) * HD])[d4] = o;
    }
}

// ---------------------------------------------------------------
// Combine split-KV partials (log-sum-exp merge) -> context [q][h*128+d]
// ---------------------------------------------------------------
__global__ void __launch_bounds__(HD) combine_kernel()
{
    int hq = blockIdx.x;                // h*QL + q
    int d = threadIdx.x;
    float mv[NCHUNK];
    float M = -FLT_MAX;
#pragma unroll
    for (int c = 0; c < NCHUNK; c++) {
        mv[c] = g_m[hq * NCHUNK + c];
        M = fmaxf(M, mv[c]);
    }
    float wf[NCHUNK];
    float denom = 0.0f;
#pragma unroll
    for (int c = 0; c < NCHUNK; c++) {
        wf[c] = __expf(mv[c] - M);
        denom += g_l[hq * NCHUNK + c] * wf[c];
    }
    float o = 0.0f;
#pragma unroll
    for (int c = 0; c < NCHUNK; c++)
        o += wf[c] * g_opart[(hq * NCHUNK + c) * HD + d];
    o /= denom;
    int h = hq / QL, q = hq % QL;
    g_ctx[q * HIDDEN + h * HD + d] = o;
}

// ---------------------------------------------------------------
extern "C" void kernel_launch(void* const* d_in, const int* in_sizes, int n_in,
                              void* d_out, int out_size)
{
    const int*   ipos  = (const int*)  d_in[0];
    const float* hs    = (const float*)d_in[1];
    const float* mask  = (const float*)d_in[2];
    const float* wpack = (const float*)d_in[3];
    const float* wo    = (const float*)d_in[4];
    const float* kc    = (const float*)d_in[5];
    const float* vc    = (const float*)d_in[6];
    float* out = (float*)d_out;

    const int smem = QL * C4 * 16;   // 163840 B
    cudaFuncSetAttribute(gemv_kernel,
                         cudaFuncAttributeMaxDynamicSharedMemorySize, smem);

    int nsm = 148;
    cudaDeviceGetAttribute(&nsm, cudaDevAttrMultiProcessorCount, 0);

    // 1) fused QKV projection -> g_q/g_k/g_v  (3840 row-groups of 4)
    gemv_kernel<<<nsm, GT, smem>>>(hs, wpack, nullptr, 0,
                                   (3 * HIDDEN) / ROWS);

    // 2) split-KV attention partials
    dim3 ag(NCHUNK, NH);
    attn_kernel<<<ag, 256>>>(kc, vc, mask, ipos);

    // 3) merge partials -> context
    combine_kernel<<<NH * QL, HD>>>();

    // 4) output projection -> d_out  (1280 row-groups of 4)
    gemv_kernel<<<nsm, GT, smem>>>(nullptr, wo, out, 1, HIDDEN / ROWS);
}

// round 16
// speedup vs baseline: 1.3987x; 1.3987x over previous
#include <cuda_runtime.h>
#include <math.h>
#include <float.h>

#define HIDDEN 5120
#define NH 40
#define HD 128
#define MAXL 2048
#define QL 8
#define CHUNK 256
#define NCHUNK (MAXL / CHUNK)
#define QK_SCALE 0.08838834764831845f  // 1/sqrt(128)
#define C4 (HIDDEN / 4)                // 1280 float4 per row
#define ROWS 8
#define GT 512                         // 128 col-slots x 4 q-pairs, 16 warps
#define COLS 128                       // float4 columns per iter
#define GITER 10                       // C4 / COLS

// packed f32x2 FMA
#define FMAX2(acc, a, b) \
    asm("fma.rn.f32x2 %0, %1, %2, %0;" : "+l"(acc) : "l"(a), "l"(b))

__device__ __forceinline__ float x2lo(unsigned long long v) {
    return __uint_as_float((unsigned)(v & 0xffffffffu));
}
__device__ __forceinline__ float x2hi(unsigned long long v) {
    return __uint_as_float((unsigned)(v >> 32));
}
__device__ __forceinline__ float x2sum(unsigned long long v) {
    return x2lo(v) + x2hi(v);
}
__device__ __forceinline__ unsigned long long f32dup(float p) {
    unsigned b = __float_as_uint(p);
    return ((unsigned long long)b << 32) | b;
}

__device__ __forceinline__ unsigned smem_u32(const void* p) {
    unsigned a;
    asm("{ .reg .u64 t; cvta.to.shared.u64 t, %1; cvt.u32.u64 %0, t; }"
        : "=r"(a) : "l"(p));
    return a;
}

// ---------------- device scratch (no allocs allowed) ----------------
__device__ float g_q[NH * QL * HD];                    // [h][q][d], pre-scaled
__device__ float g_k[NH * QL * HD];                    // new K rows  [h][q][d]
__device__ float g_v[NH * QL * HD];                    // new V rows  [h][q][d]
__device__ float g_opart[NH * QL * NCHUNK * HD];       // [h][q][chunk][d]
__device__ float g_m[NH * QL * NCHUNK];                // chunk max
__device__ float g_l[NH * QL * NCHUNK];                // chunk expsum
__device__ float g_ctx[QL * HIDDEN];                   // attention out [q][h*128+d]

// ---------------------------------------------------------------
// Persistent GEMV, M=8: Y[q][r] = dot(X[q], W[r]).
// The port-balanced + pipelined + f32x2 design:
//  - thread (cl, qp): column slot cl (0..127), q-pair qp (0..3)
//  - W tile 8 rows x 128 float4-cols per iter streams via cp.async into
//    3-stage smem slots; thread ISSUES rows {2qp, 2qp+1} at column cl
//    and CONSUMES rows 0..7 at column cl -- the writers are the 4
//    qp-lanes of the SAME warp, so wait_group + __syncwarp suffices
//    (fixes R10's cross-warp race). W LDS is 4-lane broadcast (unique
//    bytes only); X LDS = 1x W bytes. Port per iter ~3x W -> 6.3 TB/s
//    ceiling. f32x2 accs: 8 rows x 2 q = 16 b64 regs.
// grid = #SMs, 1 CTA/SM, 16 warps (4/SMSP).
// mode 0: W_pack -> g_q/g_k/g_v.  mode 1: W_o, X=g_ctx -> Y.
// Dynamic smem = 160K (X) + 48K (W stages) = 212992 B (opt-in).
// ---------------------------------------------------------------
__global__ void __launch_bounds__(GT, 1) gemv_kernel(
    const float* __restrict__ Xin, const float* __restrict__ W,
    float* __restrict__ Y, int mode, int ngrp)
{
    extern __shared__ float4 smem4[];
    float4* sX4 = smem4;                         // [QL * C4]
    float4* sW4 = smem4 + QL * C4;               // [3][ROWS][COLS]
    __shared__ float sred[16][64];               // 16 warps x (8r * 8q)

    int tid = threadIdx.x, bid = blockIdx.x, grid = gridDim.x;
    int qp = tid & 3;                            // q-pair 0..3
    int cl = tid >> 2;                           // column slot 0..127
    int lane = tid & 31, warp = tid >> 5;
    int q0 = qp * 2;
    const float4* __restrict__ X4 =
        reinterpret_cast<const float4*>((mode == 1) ? g_ctx : Xin);

    // ---- X preload (one-time; plain ldg+sts) ----
#pragma unroll
    for (int i = 0; i < (QL * C4) / GT; i++) {
        int idx = tid + i * GT;
        sX4[idx] = __ldg(X4 + idx);
    }

    unsigned wsbase = smem_u32(sW4);
    int nloc = (ngrp - bid - 1) / grid + 1;      // groups owned by this CTA
    int total = nloc * GITER;

    // issue logical iter idx (or empty commit) into stage idx%3.
    // Thread copies W rows {2qp, 2qp+1} at its column cl (2 x 16B).
    auto issue = [&](int idx) {
        if (idx < total) {
            int j = idx / GITER, iti = idx - j * GITER;
            int st = idx % 3;
            size_t rowbase = (size_t)(bid + (size_t)j * grid) * ROWS;
#pragma unroll
            for (int k = 0; k < 2; k++) {
                int r = 2 * qp + k;
                const float* g = W + (rowbase + r) * HIDDEN
                                   + (iti * COLS + cl) * 4;
                unsigned sa = wsbase +
                    (unsigned)((st * ROWS + r) * COLS + cl) * 16;
                asm volatile("cp.async.cg.shared.global [%0], [%1], 16;"
                             :: "r"(sa), "l"(g));
            }
        }
        asm volatile("cp.async.commit_group;");   // empty group if past end
    };

    issue(0); issue(1); issue(2);
    __syncthreads();                              // X visible to all

    unsigned long long acc[ROWS][2];              // f32x2 column pairs
#pragma unroll
    for (int r = 0; r < ROWS; r++) { acc[r][0] = 0ull; acc[r][1] = 0ull; }

    for (int n = 0; n < total; n++) {
        int j = n / GITER, it = n - j * GITER;
        int st = n % 3;

        asm volatile("cp.async.wait_group 2;");   // warp's groups <= n done
        __syncwarp();                              // same-warp visibility

        // W rows 0..7 at column cl (4-lane broadcast within warp)
        ulonglong2 wv[ROWS];
#pragma unroll
        for (int r = 0; r < ROWS; r++) {
            unsigned sa = wsbase +
                (unsigned)((st * ROWS + r) * COLS + cl) * 16;
            asm volatile("ld.shared.v4.f32 {%0,%1,%2,%3}, [%4];"
                         : "=f"(((float2*)&wv[r].x)->x),
                           "=f"(((float2*)&wv[r].x)->y),
                           "=f"(((float2*)&wv[r].y)->x),
                           "=f"(((float2*)&wv[r].y)->y) : "r"(sa));
        }
        int c4 = cl + it * COLS;
        ulonglong2 xa = *reinterpret_cast<const ulonglong2*>(
            &sX4[q0 * C4 + c4]);
        ulonglong2 xb = *reinterpret_cast<const ulonglong2*>(
            &sX4[(q0 + 1) * C4 + c4]);

#pragma unroll
        for (int r = 0; r < ROWS; r++) {
            FMAX2(acc[r][0], wv[r].x, xa.x);
            FMAX2(acc[r][0], wv[r].y, xa.y);
            FMAX2(acc[r][1], wv[r].x, xb.x);
            FMAX2(acc[r][1], wv[r].y, xb.y);
        }

        issue(n + 3);   // overwrites stage consumed THIS iter by own warp:
                        // LDS issued before LDGSTS in program order -> safe

        if (it == GITER - 1) {
            // ---- flush group j: 64 outputs across the block ----
            long rowbase = (long)(bid + (long)j * grid) * ROWS;
            __syncthreads();   // protect sred from prev group's readers
#pragma unroll
            for (int r = 0; r < ROWS; r++) {
#pragma unroll
                for (int s = 0; s < 2; s++) {
                    float v = x2sum(acc[r][s]);
                    v += __shfl_down_sync(0xffffffffu, v, 16);
                    v += __shfl_down_sync(0xffffffffu, v, 8);
                    v += __shfl_down_sync(0xffffffffu, v, 4);
                    if (lane < 4)
                        sred[warp][r * QL + lane * 2 + s] = v;
                    acc[r][s] = 0ull;
                }
            }
            __syncthreads();
            if (tid < 64) {
                float v = 0.0f;
#pragma unroll
                for (int w = 0; w < 16; w++) v += sred[w][tid];
                long r = rowbase + (tid >> 3);
                int q = tid & 7;
                if (mode == 0) {
                    int sect = (int)(r / HIDDEN);      // 0=q, 1=k, 2=v
                    int f = (int)(r % HIDDEN);
                    int h = f / HD, d = f % HD;
                    int o = (h * QL + q) * HD + d;
                    if (sect == 0)      g_q[o] = v * QK_SCALE;
                    else if (sect == 1) g_k[o] = v;
                    else                g_v[o] = v;
                } else {
                    Y[(long)q * HIDDEN + r] = v;
                }
            }
        }
    }
}

// ---------------------------------------------------------------
// Split-KV attention: block = (chunk of 256 keys, head). f32x2 in both
// matmul phases; probs stored pre-duplicated (p,p) in smem for PV phase.
// ---------------------------------------------------------------
__global__ void __launch_bounds__(256) attn_kernel(
    const float* __restrict__ kc, const float* __restrict__ vc,
    const float* __restrict__ mask, const int* __restrict__ ipos)
{
    int chunk = blockIdx.x;
    int h = blockIdx.y;
    int tid = threadIdx.x;
    int warp = tid >> 5, lane = tid & 31;

    __shared__ float qs[QL][HD];                    // 4 KB
    __shared__ float scf[QL][CHUNK];                // 8 KB scores
    __shared__ unsigned long long sc2[QL][CHUNK];   // 16 KB dup probs
    __shared__ float4 red[8][QL][32];               // 32 KB partial O
    __shared__ int pos[QL];
    __shared__ int sel[CHUNK];

    if (tid == 0) {
        bool is64 = (ipos[1] == 0);     // int64 little-endian high word
#pragma unroll
        for (int j = 0; j < QL; j++) pos[j] = is64 ? ipos[2 * j] : ipos[j];
    }
    for (int i = tid; i < QL * HD; i += 256) qs[0][i] = g_q[h * QL * HD + i];
    __syncthreads();

    // ---- scores: one key per thread, f32x2 pairs over d ----
    int key = chunk * CHUNK + tid;
    int s = -1;
#pragma unroll
    for (int j = 0; j < QL; j++) if (pos[j] == key) s = j;
    sel[tid] = s;

    const ulonglong2* kp = reinterpret_cast<const ulonglong2*>(
        (s >= 0) ? &g_k[(h * QL + s) * HD]
                 : &kc[((size_t)h * MAXL + key) * HD]);
    unsigned long long a2[QL];
#pragma unroll
    for (int q = 0; q < QL; q++) a2[q] = 0ull;
#pragma unroll
    for (int c = 0; c < HD / 4; c += 8) {
        ulonglong2 kv[8];
#pragma unroll
        for (int u = 0; u < 8; u++) kv[u] = __ldcg(kp + c + u);
#pragma unroll
        for (int u = 0; u < 8; u++) {
#pragma unroll
            for (int q = 0; q < QL; q++) {
                ulonglong2 qv = *reinterpret_cast<const ulonglong2*>(
                    &qs[q][(c + u) * 4]);
                FMAX2(a2[q], kv[u].x, qv.x);
                FMAX2(a2[q], kv[u].y, qv.y);
            }
        }
    }
#pragma unroll
    for (int q = 0; q < QL; q++) {
        float m = __ldcg(&mask[((size_t)h * MAXL + pos[q]) * MAXL + key]);
        scf[q][tid] = fmaxf(x2sum(a2[q]) + m, -FLT_MAX);
    }
    __syncthreads();

    // ---- softmax stats: warp q handles query q; write dup probs ----
    {
        float m = -FLT_MAX;
#pragma unroll
        for (int i = 0; i < CHUNK / 32; i++) m = fmaxf(m, scf[warp][lane + i * 32]);
#pragma unroll
        for (int o = 16; o > 0; o >>= 1) m = fmaxf(m, __shfl_xor_sync(0xffffffffu, m, o));
        float l = 0.0f;
#pragma unroll
        for (int i = 0; i < CHUNK / 32; i++) {
            float p = __expf(scf[warp][lane + i * 32] - m);
            sc2[warp][lane + i * 32] = f32dup(p);
            l += p;
        }
#pragma unroll
        for (int o = 16; o > 0; o >>= 1) l += __shfl_xor_sync(0xffffffffu, l, o);
        if (lane == 0) {
            g_m[(h * QL + warp) * NCHUNK + chunk] = m;
            g_l[(h * QL + warp) * NCHUNK + chunk] = l;
        }
    }
    __syncthreads();

    // ---- partial O = P^T V. warp w: keys w,w+8,...; lane: d-float4 ----
    unsigned long long acc[QL][2];     // 2 d-pairs per lane
#pragma unroll
    for (int q = 0; q < QL; q++) { acc[q][0] = 0ull; acc[q][1] = 0ull; }

#pragma unroll
    for (int j = 0; j < 32; j += 4) {
        ulonglong2 vv[4];
#pragma unroll
        for (int u = 0; u < 4; u++) {
            int k = warp + 8 * (j + u);
            int sv = sel[k];
            int kk = chunk * CHUNK + k;
            const ulonglong2* vp = reinterpret_cast<const ulonglong2*>(
                (sv >= 0) ? &g_v[(h * QL + sv) * HD]
                          : &vc[((size_t)h * MAXL + kk) * HD]);
            vv[u] = __ldcg(vp + lane);
        }
#pragma unroll
        for (int u = 0; u < 4; u++) {
            int k = warp + 8 * (j + u);
#pragma unroll
            for (int q = 0; q < QL; q++) {
                unsigned long long p2 = sc2[q][k];
                FMAX2(acc[q][0], p2, vv[u].x);
                FMAX2(acc[q][1], p2, vv[u].y);
            }
        }
    }
#pragma unroll
    for (int q = 0; q < QL; q++)
        red[warp][q][lane] = make_float4(x2lo(acc[q][0]), x2hi(acc[q][0]),
                                         x2lo(acc[q][1]), x2hi(acc[q][1]));
    __syncthreads();

    // reduce 8 warps: thread t handles (q, d4) = (t/32, t%32)
    {
        int q = tid >> 5, d4 = tid & 31;
        float4 o = red[0][q][d4];
#pragma unroll
        for (int w = 1; w < 8; w++) {
            float4 v = red[w][q][d4];
            o.x += v.x; o.y += v.y; o.z += v.z; o.w += v.w;
        }
        reinterpret_cast<float4*>(
            &g_opart[((h * QL + q) * NCHUNK + chunk) * HD])[d4] = o;
    }
}

// ---------------------------------------------------------------
// Combine split-KV partials (log-sum-exp merge) -> context [q][h*128+d]
// ---------------------------------------------------------------
__global__ void __launch_bounds__(HD) combine_kernel()
{
    int hq = blockIdx.x;                // h*QL + q
    int d = threadIdx.x;
    float mv[NCHUNK];
    float M = -FLT_MAX;
#pragma unroll
    for (int c = 0; c < NCHUNK; c++) {
        mv[c] = g_m[hq * NCHUNK + c];
        M = fmaxf(M, mv[c]);
    }
    float wf[NCHUNK];
    float denom = 0.0f;
#pragma unroll
    for (int c = 0; c < NCHUNK; c++) {
        wf[c] = __expf(mv[c] - M);
        denom += g_l[hq * NCHUNK + c] * wf[c];
    }
    float o = 0.0f;
#pragma unroll
    for (int c = 0; c < NCHUNK; c++)
        o += wf[c] * g_opart[(hq * NCHUNK + c) * HD + d];
    o /= denom;
    int h = hq / QL, q = hq % QL;
    g_ctx[q * HIDDEN + h * HD + d] = o;
}

// ---------------------------------------------------------------
extern "C" void kernel_launch(void* const* d_in, const int* in_sizes, int n_in,
                              void* d_out, int out_size)
{
    const int*   ipos  = (const int*)  d_in[0];
    const float* hs    = (const float*)d_in[1];
    const float* mask  = (const float*)d_in[2];
    const float* wpack = (const float*)d_in[3];
    const float* wo    = (const float*)d_in[4];
    const float* kc    = (const float*)d_in[5];
    const float* vc    = (const float*)d_in[6];
    float* out = (float*)d_out;

    const int smem = (QL * C4 + 3 * ROWS * COLS) * 16;   // 212992 B
    cudaFuncSetAttribute(gemv_kernel,
                         cudaFuncAttributeMaxDynamicSharedMemorySize, smem);

    int nsm = 148;
    cudaDeviceGetAttribute(&nsm, cudaDevAttrMultiProcessorCount, 0);

    // 1) fused QKV projection -> g_q/g_k/g_v  (1920 row-groups of 8)
    gemv_kernel<<<nsm, GT, smem>>>(hs, wpack, nullptr, 0,
                                   (3 * HIDDEN) / ROWS);

    // 2) split-KV attention partials
    dim3 ag(NCHUNK, NH);
    attn_kernel<<<ag, 256>>>(kc, vc, mask, ipos);

    // 3) merge partials -> context
    combine_kernel<<<NH * QL, HD>>>();

    // 4) output projection -> d_out  (640 row-groups of 8)
    gemv_kernel<<<nsm, GT, smem>>>(nullptr, wo, out, 1, HIDDEN / ROWS);
}